// round 13
// baseline (speedup 1.0000x reference)
#include <cuda_runtime.h>
#include <math.h>

// Problem shapes (fixed by the dataset)
#define N_Q 256      // queries
#define DIM 512      // feature dim
#define QB  2048     // bank size
#define NC  1000     // classes
#define IMG 150528   // 3*224*224
#define IMG4 (IMG/4) // 37632 float4 per image
#define KNN 4

// Output layout (float32, concatenated in reference return order)
#define OFF_LBL 0
#define OFF_PRB 256
#define OFF_IMG 256256           // 256 + 256*1000
#define OFF_GRD 38791424         // OFF_IMG + 256*150528

#define BM 64
#define BN 64
#define BK 32
#define NT (DIM / BK)            // 16 k-tiles
#define NBX (QB / BN)            // 32 bank-tile CTAs per query row
#define BMp 65                   // padded smem stride: conflict-free STS

// Scratch (static device globals — no allocations allowed)
__device__ float g_pv[N_Q * NBX * 4];   // partial top-4 scores per (q, col-block)
__device__ int   g_pi[N_Q * NBX * 4];   // partial top-4 indices
__device__ int   g_idx[N_Q * KNN];      // final neighbor indices
__device__ int   g_cnt[N_Q / BM];       // last-CTA counters (self-resetting)

// ---------------------------------------------------------------------------
// top-4 helpers: largest-first, ties -> smaller index (lax.top_k order)
// ---------------------------------------------------------------------------
__device__ __forceinline__ bool d_better(float v, int j, float v2, int j2) {
    return (v > v2) || (v == v2 && j < j2);
}
__device__ __forceinline__ void d_insert(float v, int j, float* bv, int* bi) {
    if (!d_better(v, j, bv[3], bi[3])) return;
    int p = 3;
    while (p > 0 && d_better(v, j, bv[p - 1], bi[p - 1])) {
        bv[p] = bv[p - 1]; bi[p] = bi[p - 1]; p--;
    }
    bv[p] = v; bi[p] = j;
}
template<int SPAN>
__device__ __forceinline__ void shfl_merge_top4(float* bv, int* bi) {
#pragma unroll
    for (int o = SPAN / 2; o; o >>= 1) {
        float pv[4]; int pi[4];
#pragma unroll
        for (int k = 0; k < 4; k++) {
            pv[k] = __shfl_xor_sync(0xffffffffu, bv[k], o);
            pi[k] = __shfl_xor_sync(0xffffffffu, bi[k], o);
        }
#pragma unroll
        for (int k = 0; k < 4; k++) d_insert(pv[k], pi[k], bv, bi);
    }
}

// ---------------------------------------------------------------------------
// K1: distance GEMM + fused bank norms + per-tile top-4 + last-CTA merge.
// Key simplification: outputs contain no distances, only neighbor indices,
// and within a query row (1 - dot*qinv*binv) is a monotone transform of
// (-dot*binv) for ANY qinv>0. So query norms are dropped entirely, and bank
// norms accumulate inside the k-loop (each thread sees all k of its 4 cols).
// Score used for selection: 1 - dot*binv  (same ranking & tie structure).
// 64x64x32 tile, 256 thr, 4x4 micro-tile, padded smem, double-buffered.
// After partials: __threadfence + atomic counter; the LAST CTA of each
// query row merges 64 queries x 128 candidates into g_idx (8 warps x 8 q),
// then resets the counter (safe under graph replay).
// grid = (QB/64, N_Q/64) = (32, 4) = 128 CTAs.
// ---------------------------------------------------------------------------
__global__ void __launch_bounds__(256)
dist_topk_kernel(const float* __restrict__ A,   // features (N_Q,DIM)
                 const float* __restrict__ B) { // bank     (QB,DIM)
    __shared__ float As[2][BK][BMp];
    __shared__ float Bs[2][BK][BMp];
    __shared__ int   s_last;

    int tid = threadIdx.x;
    int tx = tid & 15;        // 0..15 -> 4 bank cols
    int ty = tid >> 4;        // 0..15 -> 4 query rows
    int qb = blockIdx.y * BM;
    int bb = blockIdx.x * BN;
    int r0 = tid >> 3;        // 0..31 (load rows r0 and r0+32)
    int c4 = tid & 7;         // 0..7  (float4 col in k-slab)

    const float4* Ag0 = (const float4*)(A + (size_t)(qb + r0)      * DIM) + c4;
    const float4* Ag1 = (const float4*)(A + (size_t)(qb + r0 + 32) * DIM) + c4;
    const float4* Bg0 = (const float4*)(B + (size_t)(bb + r0)      * DIM) + c4;
    const float4* Bg1 = (const float4*)(B + (size_t)(bb + r0 + 32) * DIM) + c4;

    float acc[4][4] = {};
    float bsq[4] = {};        // per-thread bank-column |b|^2 (full k range)

    float4 va0 = Ag0[0], va1 = Ag1[0], vb0 = Bg0[0], vb1 = Bg1[0];
    // store tile 0 -> buffer 0 (transposed; stride 65 -> conflict-free)
    {
        As[0][c4 * 4 + 0][r0] = va0.x; As[0][c4 * 4 + 1][r0] = va0.y;
        As[0][c4 * 4 + 2][r0] = va0.z; As[0][c4 * 4 + 3][r0] = va0.w;
        As[0][c4 * 4 + 0][r0 + 32] = va1.x; As[0][c4 * 4 + 1][r0 + 32] = va1.y;
        As[0][c4 * 4 + 2][r0 + 32] = va1.z; As[0][c4 * 4 + 3][r0 + 32] = va1.w;
        Bs[0][c4 * 4 + 0][r0] = vb0.x; Bs[0][c4 * 4 + 1][r0] = vb0.y;
        Bs[0][c4 * 4 + 2][r0] = vb0.z; Bs[0][c4 * 4 + 3][r0] = vb0.w;
        Bs[0][c4 * 4 + 0][r0 + 32] = vb1.x; Bs[0][c4 * 4 + 1][r0 + 32] = vb1.y;
        Bs[0][c4 * 4 + 2][r0 + 32] = vb1.z; Bs[0][c4 * 4 + 3][r0 + 32] = vb1.w;
    }
    __syncthreads();

    for (int t = 0; t < NT; t++) {
        if (t + 1 < NT) {                 // prefetch next tile into registers
            va0 = Ag0[(t + 1) * (BK / 4)]; va1 = Ag1[(t + 1) * (BK / 4)];
            vb0 = Bg0[(t + 1) * (BK / 4)]; vb1 = Bg1[(t + 1) * (BK / 4)];
        }
        int cur = t & 1;
#pragma unroll
        for (int k = 0; k < BK; k++) {
            float ra[4], rb[4];
#pragma unroll
            for (int i = 0; i < 4; i++) ra[i] = As[cur][k][ty * 4 + i];
#pragma unroll
            for (int j = 0; j < 4; j++) rb[j] = Bs[cur][k][tx * 4 + j];
#pragma unroll
            for (int j = 0; j < 4; j++) bsq[j] = fmaf(rb[j], rb[j], bsq[j]);
#pragma unroll
            for (int i = 0; i < 4; i++)
#pragma unroll
                for (int j = 0; j < 4; j++)
                    acc[i][j] = fmaf(ra[i], rb[j], acc[i][j]);
        }
        if (t + 1 < NT) {                 // store prefetch -> other buffer
            int nb = (t + 1) & 1;
            As[nb][c4 * 4 + 0][r0] = va0.x; As[nb][c4 * 4 + 1][r0] = va0.y;
            As[nb][c4 * 4 + 2][r0] = va0.z; As[nb][c4 * 4 + 3][r0] = va0.w;
            As[nb][c4 * 4 + 0][r0 + 32] = va1.x; As[nb][c4 * 4 + 1][r0 + 32] = va1.y;
            As[nb][c4 * 4 + 2][r0 + 32] = va1.z; As[nb][c4 * 4 + 3][r0 + 32] = va1.w;
            Bs[nb][c4 * 4 + 0][r0] = vb0.x; Bs[nb][c4 * 4 + 1][r0] = vb0.y;
            Bs[nb][c4 * 4 + 2][r0] = vb0.z; Bs[nb][c4 * 4 + 3][r0] = vb0.w;
            Bs[nb][c4 * 4 + 0][r0 + 32] = vb1.x; Bs[nb][c4 * 4 + 1][r0 + 32] = vb1.y;
            Bs[nb][c4 * 4 + 2][r0 + 32] = vb1.z; Bs[nb][c4 * 4 + 3][r0 + 32] = vb1.w;
        }
        __syncthreads();
    }

    // Epilogue: scores (1 - dot*binv; qinv dropped, ranking-equivalent)
    float binv[4];
#pragma unroll
    for (int j = 0; j < 4; j++) binv[j] = 1.0f / fmaxf(sqrtf(bsq[j]), 1e-12f);

#pragma unroll
    for (int i = 0; i < 4; i++) {
        int q = qb + ty * 4 + i;
        float bv[4] = {-3.0e38f, -3.0e38f, -3.0e38f, -3.0e38f};
        int   bi[4] = {0x7fffffff, 0x7fffffff, 0x7fffffff, 0x7fffffff};
        int b0 = bb + tx * 4;
#pragma unroll
        for (int j = 0; j < 4; j++)
            d_insert(1.0f - acc[i][j] * binv[j], b0 + j, bv, bi);
        shfl_merge_top4<16>(bv, bi);   // across the 16 tx lanes of this row
        if (tx == 0) {
            int base = (q * NBX + blockIdx.x) * 4;
#pragma unroll
            for (int k = 0; k < 4; k++) { g_pv[base + k] = bv[k]; g_pi[base + k] = bi[k]; }
        }
    }

    // ---- last-CTA final merge for this query row (replaces merge kernel) ----
    __threadfence();
    __syncthreads();
    if (tid == 0) {
        int prev = atomicAdd(&g_cnt[blockIdx.y], 1);
        s_last = (prev == NBX - 1);
    }
    __syncthreads();
    if (s_last) {
        int lane = tid & 31, w = tid >> 5;       // 8 warps x 8 queries each
#pragma unroll
        for (int s = 0; s < 8; s++) {
            int q = qb + w * 8 + s;
            float4 v = ((const float4*)(g_pv + q * NBX * 4))[lane];
            int4   j = ((const int4*)  (g_pi + q * NBX * 4))[lane];
            float bv[4] = {-3.0e38f, -3.0e38f, -3.0e38f, -3.0e38f};
            int   bi[4] = {0x7fffffff, 0x7fffffff, 0x7fffffff, 0x7fffffff};
            d_insert(v.x, j.x, bv, bi);
            d_insert(v.y, j.y, bv, bi);
            d_insert(v.z, j.z, bv, bi);
            d_insert(v.w, j.w, bv, bi);
            shfl_merge_top4<32>(bv, bi);
            if (lane < 4) g_idx[q * 4 + lane] = bi[lane];
        }
        if (tid == 0) atomicExch(&g_cnt[blockIdx.y], 0);   // replay-safe reset
    }
}

// ---------------------------------------------------------------------------
// K2: fused gather (proven 92.8us / 83% DRAM version — no merge prologue).
// grid=(256, 22), 256 threads.
//   blockIdx.y < 21 : pred_images chunk (HBM-bound bulk)
//   blockIdx.y ==21 : grads_m + pred_probs + pred_labels (hidden in the wave)
// ---------------------------------------------------------------------------
__global__ void gather_kernel(const float* __restrict__ img,
                              const float* __restrict__ bank,
                              const float* __restrict__ probs,
                              float* __restrict__ out) {
    int q = blockIdx.x;
    int tid = threadIdx.x;
    __shared__ int ix[4];
    if (tid < 4) ix[tid] = g_idx[q * 4 + tid];
    __syncthreads();

    if (blockIdx.y < 21) {
        const float4* im = (const float4*)img;
        float4* o = (float4*)(out + OFF_IMG) + (size_t)q * IMG4;
        size_t r0 = (size_t)ix[0] * IMG4;
        size_t r1 = (size_t)ix[1] * IMG4;
        size_t r2 = (size_t)ix[2] * IMG4;
        size_t r3 = (size_t)ix[3] * IMG4;
#pragma unroll
        for (int t = 0; t < 7; t++) {
            int f = blockIdx.y * 1792 + t * 256 + tid;   // 21*1792 = 37632 = IMG4
            float4 a = im[r0 + f];
            float4 b = im[r1 + f];
            float4 c = im[r2 + f];
            float4 d = im[r3 + f];
            float4 r;
            r.x = 0.25f * (a.x + b.x + c.x + d.x);
            r.y = 0.25f * (a.y + b.y + c.y + d.y);
            r.z = 0.25f * (a.z + b.z + c.z + d.z);
            r.w = 0.25f * (a.w + b.w + c.w + d.w);
            __stcs(&o[f], r);   // streaming store: no reuse of output
        }
        return;
    }

    // ---- small outputs slice ----
    if (tid < 128) {
        const float4* b0 = (const float4*)(bank + (size_t)ix[0] * DIM);
        const float4* b1 = (const float4*)(bank + (size_t)ix[1] * DIM);
        const float4* b2 = (const float4*)(bank + (size_t)ix[2] * DIM);
        const float4* b3 = (const float4*)(bank + (size_t)ix[3] * DIM);
        float4 a = b0[tid], b = b1[tid], c = b2[tid], d = b3[tid];
        float4 r;
        r.x = 0.25f * (a.x + b.x + c.x + d.x);
        r.y = 0.25f * (a.y + b.y + c.y + d.y);
        r.z = 0.25f * (a.z + b.z + c.z + d.z);
        r.w = 0.25f * (a.w + b.w + c.w + d.w);
        ((float4*)(out + OFF_GRD + (size_t)q * DIM))[tid] = r;
    }

    float bestv = -3.0e38f;
    int   bestc = 0x7fffffff;
    if (tid < 250) {
        const float4* p0 = (const float4*)(probs + (size_t)ix[0] * NC);
        const float4* p1 = (const float4*)(probs + (size_t)ix[1] * NC);
        const float4* p2 = (const float4*)(probs + (size_t)ix[2] * NC);
        const float4* p3 = (const float4*)(probs + (size_t)ix[3] * NC);
        float4 a = p0[tid], b = p1[tid], c = p2[tid], d = p3[tid];
        float4 m;
        m.x = 0.25f * (a.x + b.x + c.x + d.x);
        m.y = 0.25f * (a.y + b.y + c.y + d.y);
        m.z = 0.25f * (a.z + b.z + c.z + d.z);
        m.w = 0.25f * (a.w + b.w + c.w + d.w);
        ((float4*)(out + OFF_PRB + (size_t)q * NC))[tid] = m;
        int c0 = tid * 4;
        bestv = m.x; bestc = c0;
        if (m.y > bestv) { bestv = m.y; bestc = c0 + 1; }
        if (m.z > bestv) { bestv = m.z; bestc = c0 + 2; }
        if (m.w > bestv) { bestv = m.w; bestc = c0 + 3; }
    }
    __shared__ float rv[256];
    __shared__ int   rc[256];
    rv[tid] = bestv; rc[tid] = bestc;
    __syncthreads();
    for (int s = 128; s; s >>= 1) {
        if (tid < s) {
            float v2 = rv[tid + s]; int c2 = rc[tid + s];
            if (v2 > rv[tid] || (v2 == rv[tid] && c2 < rc[tid])) {
                rv[tid] = v2; rc[tid] = c2;
            }
        }
        __syncthreads();
    }
    if (tid == 0) out[OFF_LBL + q] = (float)rc[0];
}

// ---------------------------------------------------------------------------
extern "C" void kernel_launch(void* const* d_in, const int* in_sizes, int n_in,
                              void* d_out, int out_size) {
    const float* feat  = (const float*)d_in[0];
    const float* bank  = (const float*)d_in[1];
    const float* probs = (const float*)d_in[2];
    const float* img   = (const float*)d_in[3];
    float* out = (float*)d_out;

    dist_topk_kernel<<<dim3(QB / BN, N_Q / BM), 256>>>(feat, bank);
    gather_kernel<<<dim3(N_Q, 22), 256>>>(img, bank, probs, out);
}

// round 14
// speedup vs baseline: 1.8286x; 1.8286x over previous
#include <cuda_runtime.h>
#include <math.h>

// Problem shapes (fixed by the dataset)
#define N_Q 256      // queries
#define DIM 512      // feature dim
#define QB  2048     // bank size
#define NC  1000     // classes
#define IMG 150528   // 3*224*224
#define IMG4 (IMG/4) // 37632 float4 per image
#define KNN 4

// Output layout (float32, concatenated in reference return order)
#define OFF_LBL 0
#define OFF_PRB 256
#define OFF_IMG 256256           // 256 + 256*1000
#define OFF_GRD 38791424         // OFF_IMG + 256*150528

#define BM 64
#define BN 64
#define BK 32
#define NBX (QB / BN)            // 32 partial top-4 blocks per query

// Scratch (static device globals — no allocations allowed)
__device__ float g_pv[N_Q * NBX * 4];   // partial top-4 scores per (q, col-block)
__device__ int   g_pi[N_Q * NBX * 4];   // partial top-4 indices
__device__ int   g_idx[N_Q * KNN];      // final neighbor indices

// ---------------------------------------------------------------------------
// top-4 helpers: largest-first, ties -> smaller index (lax.top_k order)
// ---------------------------------------------------------------------------
__device__ __forceinline__ bool d_better(float v, int j, float v2, int j2) {
    return (v > v2) || (v == v2 && j < j2);
}
__device__ __forceinline__ void d_insert(float v, int j, float* bv, int* bi) {
    if (!d_better(v, j, bv[3], bi[3])) return;
    int p = 3;
    while (p > 0 && d_better(v, j, bv[p - 1], bi[p - 1])) {
        bv[p] = bv[p - 1]; bi[p] = bi[p - 1]; p--;
    }
    bv[p] = v; bi[p] = j;
}
template<int SPAN>
__device__ __forceinline__ void shfl_merge_top4(float* bv, int* bi) {
#pragma unroll
    for (int o = SPAN / 2; o; o >>= 1) {
        float pv[4]; int pi[4];
#pragma unroll
        for (int k = 0; k < 4; k++) {
            pv[k] = __shfl_xor_sync(0xffffffffu, bv[k], o);
            pi[k] = __shfl_xor_sync(0xffffffffu, bi[k], o);
        }
#pragma unroll
        for (int k = 0; k < 4; k++) d_insert(pv[k], pi[k], bv, bi);
    }
}

// ---------------------------------------------------------------------------
// K1: distance GEMM + fused bank norms + per-tile top-4 partials.
// GEMM core is the R4/144.0 version VERBATIM (64x64x32, 256 thr, 4x4
// micro-tile, single-buffered smem, two barriers per tile).
// Bank norms: each loading thread squares its own B float4 at load time
// (no extra LDS, outside the FMA loop's register window), folded across the
// 8 c4-chunks by a 3-round warp shuffle after the k-loop -> sBinv.
// Scoring: qinv dropped (monotone-rank equivalent, proven R12/R13):
//   score = 1 - dot*binv, largest-first, ties -> smaller index.
// Epilogue: R5-proven per-row top-4 partials -> g_pv/g_pi. No merge tail,
// no atomics (R13's register-bloat mechanism removed).
// grid = (QB/64, N_Q/64) = (32, 4) = 128 CTAs.
// ---------------------------------------------------------------------------
__global__ void __launch_bounds__(256)
dist_topk_kernel(const float* __restrict__ A,   // features (N_Q,DIM)
                 const float* __restrict__ B) { // bank     (QB,DIM)
    __shared__ float As[BK][BM];
    __shared__ float Bs[BK][BN];
    __shared__ float sBinv[BN];
    int tid = threadIdx.x;
    int tx = tid & 15;
    int ty = tid >> 4;
    int qb = blockIdx.y * BM;
    int bb = blockIdx.x * BN;

    float acc[4][4] = {};
    float ssq_lo = 0.f, ssq_hi = 0.f;   // |b|^2 partials for B rows (tid>>3), +32

    for (int k0 = 0; k0 < DIM; k0 += BK) {
#pragma unroll
        for (int l = 0; l < 2; l++) {
            int i  = tid + l * 256;   // float4 index 0..511
            int r  = i >> 3;          // row in tile 0..63
            int c4 = i & 7;           // float4 col 0..7
            float4 v = *(const float4*)(A + (size_t)(qb + r) * DIM + k0 + c4 * 4);
            As[c4 * 4 + 0][r] = v.x; As[c4 * 4 + 1][r] = v.y;
            As[c4 * 4 + 2][r] = v.z; As[c4 * 4 + 3][r] = v.w;
            float4 w = *(const float4*)(B + (size_t)(bb + r) * DIM + k0 + c4 * 4);
            Bs[c4 * 4 + 0][r] = w.x; Bs[c4 * 4 + 1][r] = w.y;
            Bs[c4 * 4 + 2][r] = w.z; Bs[c4 * 4 + 3][r] = w.w;
            float s = w.x * w.x + w.y * w.y + w.z * w.z + w.w * w.w;
            if (l == 0) ssq_lo += s; else ssq_hi += s;
        }
        __syncthreads();
#pragma unroll
        for (int k = 0; k < BK; k++) {
            float ra[4], rb[4];
#pragma unroll
            for (int i = 0; i < 4; i++) ra[i] = As[k][ty * 4 + i];
#pragma unroll
            for (int j = 0; j < 4; j++) rb[j] = Bs[k][tx * 4 + j];
#pragma unroll
            for (int i = 0; i < 4; i++)
#pragma unroll
                for (int j = 0; j < 4; j++)
                    acc[i][j] = fmaf(ra[i], rb[j], acc[i][j]);
        }
        __syncthreads();
    }

    // fold B-row squared sums across the 8 c4-chunks (lanes tid&7)
#pragma unroll
    for (int o = 1; o < 8; o <<= 1) {
        ssq_lo += __shfl_xor_sync(0xffffffffu, ssq_lo, o);
        ssq_hi += __shfl_xor_sync(0xffffffffu, ssq_hi, o);
    }
    if ((tid & 7) == 0) {
        int r = tid >> 3;                 // 0..31
        sBinv[r]      = 1.0f / fmaxf(sqrtf(ssq_lo), 1e-12f);
        sBinv[r + 32] = 1.0f / fmaxf(sqrtf(ssq_hi), 1e-12f);
    }
    __syncthreads();

    // Epilogue: scores + per-row top-4 over this CTA's 64 columns.
    float bj[4];
#pragma unroll
    for (int j = 0; j < 4; j++) bj[j] = sBinv[tx * 4 + j];

#pragma unroll
    for (int i = 0; i < 4; i++) {
        int q = qb + ty * 4 + i;
        float bv[4] = {-3.0e38f, -3.0e38f, -3.0e38f, -3.0e38f};
        int   bi[4] = {0x7fffffff, 0x7fffffff, 0x7fffffff, 0x7fffffff};
        int b0 = bb + tx * 4;
#pragma unroll
        for (int j = 0; j < 4; j++)
            d_insert(1.0f - acc[i][j] * bj[j], b0 + j, bv, bi);
        shfl_merge_top4<16>(bv, bi);   // across the 16 tx lanes of this row
        if (tx == 0) {
            int base = (q * NBX + blockIdx.x) * 4;
#pragma unroll
            for (int k = 0; k < 4; k++) { g_pv[base + k] = bv[k]; g_pi[base + k] = bi[k]; }
        }
    }
}

// ---------------------------------------------------------------------------
// K2: final top-4 merge. One warp per query folds 32 partials x 4 = 128
// candidates. 32 blocks x 256 threads (8 warps each).
// ---------------------------------------------------------------------------
__global__ void merge_topk_kernel() {
    int tid  = threadIdx.x;
    int lane = tid & 31, wid = tid >> 5;
    int q = blockIdx.x * 8 + wid;

    const float4* pv4 = (const float4*)(g_pv + q * NBX * 4);
    const int4*   pi4 = (const int4*)  (g_pi + q * NBX * 4);
    float4 v = pv4[lane];   // 128 candidates = 1 float4 per lane
    int4   j = pi4[lane];

    float bv[4] = {-3.0e38f, -3.0e38f, -3.0e38f, -3.0e38f};
    int   bi[4] = {0x7fffffff, 0x7fffffff, 0x7fffffff, 0x7fffffff};
    d_insert(v.x, j.x, bv, bi);
    d_insert(v.y, j.y, bv, bi);
    d_insert(v.z, j.z, bv, bi);
    d_insert(v.w, j.w, bv, bi);
    shfl_merge_top4<32>(bv, bi);
    if (lane < 4) g_idx[q * 4 + lane] = bi[lane];
}

// ---------------------------------------------------------------------------
// K3: fused gather (proven 92.8us / 83% DRAM version).
// grid=(256, 22), 256 threads.
//   blockIdx.y < 21 : pred_images chunk (HBM-bound bulk)
//   blockIdx.y ==21 : grads_m + pred_probs + pred_labels (hidden in the wave)
// ---------------------------------------------------------------------------
__global__ void gather_kernel(const float* __restrict__ img,
                              const float* __restrict__ bank,
                              const float* __restrict__ probs,
                              float* __restrict__ out) {
    int q = blockIdx.x;
    int tid = threadIdx.x;
    __shared__ int ix[4];
    if (tid < 4) ix[tid] = g_idx[q * 4 + tid];
    __syncthreads();

    if (blockIdx.y < 21) {
        const float4* im = (const float4*)img;
        float4* o = (float4*)(out + OFF_IMG) + (size_t)q * IMG4;
        size_t r0 = (size_t)ix[0] * IMG4;
        size_t r1 = (size_t)ix[1] * IMG4;
        size_t r2 = (size_t)ix[2] * IMG4;
        size_t r3 = (size_t)ix[3] * IMG4;
#pragma unroll
        for (int t = 0; t < 7; t++) {
            int f = blockIdx.y * 1792 + t * 256 + tid;   // 21*1792 = 37632 = IMG4
            float4 a = im[r0 + f];
            float4 b = im[r1 + f];
            float4 c = im[r2 + f];
            float4 d = im[r3 + f];
            float4 r;
            r.x = 0.25f * (a.x + b.x + c.x + d.x);
            r.y = 0.25f * (a.y + b.y + c.y + d.y);
            r.z = 0.25f * (a.z + b.z + c.z + d.z);
            r.w = 0.25f * (a.w + b.w + c.w + d.w);
            __stcs(&o[f], r);   // streaming store: no reuse of output
        }
        return;
    }

    // ---- small outputs slice ----
    if (tid < 128) {
        const float4* b0 = (const float4*)(bank + (size_t)ix[0] * DIM);
        const float4* b1 = (const float4*)(bank + (size_t)ix[1] * DIM);
        const float4* b2 = (const float4*)(bank + (size_t)ix[2] * DIM);
        const float4* b3 = (const float4*)(bank + (size_t)ix[3] * DIM);
        float4 a = b0[tid], b = b1[tid], c = b2[tid], d = b3[tid];
        float4 r;
        r.x = 0.25f * (a.x + b.x + c.x + d.x);
        r.y = 0.25f * (a.y + b.y + c.y + d.y);
        r.z = 0.25f * (a.z + b.z + c.z + d.z);
        r.w = 0.25f * (a.w + b.w + c.w + d.w);
        ((float4*)(out + OFF_GRD + (size_t)q * DIM))[tid] = r;
    }

    float bestv = -3.0e38f;
    int   bestc = 0x7fffffff;
    if (tid < 250) {
        const float4* p0 = (const float4*)(probs + (size_t)ix[0] * NC);
        const float4* p1 = (const float4*)(probs + (size_t)ix[1] * NC);
        const float4* p2 = (const float4*)(probs + (size_t)ix[2] * NC);
        const float4* p3 = (const float4*)(probs + (size_t)ix[3] * NC);
        float4 a = p0[tid], b = p1[tid], c = p2[tid], d = p3[tid];
        float4 m;
        m.x = 0.25f * (a.x + b.x + c.x + d.x);
        m.y = 0.25f * (a.y + b.y + c.y + d.y);
        m.z = 0.25f * (a.z + b.z + c.z + d.z);
        m.w = 0.25f * (a.w + b.w + c.w + d.w);
        ((float4*)(out + OFF_PRB + (size_t)q * NC))[tid] = m;
        int c0 = tid * 4;
        bestv = m.x; bestc = c0;
        if (m.y > bestv) { bestv = m.y; bestc = c0 + 1; }
        if (m.z > bestv) { bestv = m.z; bestc = c0 + 2; }
        if (m.w > bestv) { bestv = m.w; bestc = c0 + 3; }
    }
    __shared__ float rv[256];
    __shared__ int   rc[256];
    rv[tid] = bestv; rc[tid] = bestc;
    __syncthreads();
    for (int s = 128; s; s >>= 1) {
        if (tid < s) {
            float v2 = rv[tid + s]; int c2 = rc[tid + s];
            if (v2 > rv[tid] || (v2 == rv[tid] && c2 < rc[tid])) {
                rv[tid] = v2; rc[tid] = c2;
            }
        }
        __syncthreads();
    }
    if (tid == 0) out[OFF_LBL + q] = (float)rc[0];
}

// ---------------------------------------------------------------------------
extern "C" void kernel_launch(void* const* d_in, const int* in_sizes, int n_in,
                              void* d_out, int out_size) {
    const float* feat  = (const float*)d_in[0];
    const float* bank  = (const float*)d_in[1];
    const float* probs = (const float*)d_in[2];
    const float* img   = (const float*)d_in[3];
    float* out = (float*)d_out;

    dist_topk_kernel<<<dim3(QB / BN, N_Q / BM), 256>>>(feat, bank);
    merge_topk_kernel<<<N_Q / 8, 256>>>();
    gather_kernel<<<dim3(N_Q, 22), 256>>>(img, bank, probs, out);
}